// round 13
// baseline (speedup 1.0000x reference)
#include <cuda_runtime.h>
#include <cuda_bf16.h>
#include <cuda_fp16.h>
#include <math.h>
#include <stdint.h>

#define BATCH 2
#define SEQ 2048
#define DIM 2048
#define NH 16
#define NKV 4
#define HD 128
#define MTOT (BATCH * SEQ)          // 4096
#define KVD (NKV * HD)              // 512
#define NQKV (DIM + 2 * KVD)        // 3072
#define WRB (DIM * 2)               // row bytes for fp16 [*, K=2048]

// ---------------- scratch (static device globals) ----------------------------
__device__ __half g_Ah  [(size_t)MTOT * DIM];   // activations fp16 (x, then attn out)
__device__ __half g_Wqkv[(size_t)NQKV * DIM];   // [WqT;WkT;WvT] fp16 [N,K]
__device__ __half g_Wo2 [(size_t)DIM  * DIM];   // WoT fp16
__device__ __half g_Qh  [(size_t)MTOT * DIM];
__device__ __half g_Kh  [(size_t)MTOT * KVD];
__device__ __half g_Vh  [(size_t)MTOT * KVD];

#define QMUL (0.08838834764831845f * 1.4426950408889634f)   // scale * log2(e)

// ======================= small PTX helpers ===================================
__device__ __forceinline__ uint32_t smem_u32(const void* p) {
    uint32_t a;
    asm("{ .reg .u64 t; cvta.to.shared.u64 t, %1; cvt.u32.u64 %0, t; }" : "=r"(a) : "l"(p));
    return a;
}
__device__ __forceinline__ void cp16(uint32_t dst, const void* src) {
    asm volatile("cp.async.cg.shared.global [%0], [%1], 16;" :: "r"(dst), "l"(src));
}
__device__ __forceinline__ void cp_commit() { asm volatile("cp.async.commit_group;"); }
template <int N> __device__ __forceinline__ void cp_wait() {
    asm volatile("cp.async.wait_group %0;" :: "n"(N));
}
__device__ __forceinline__ void ldmx4(uint32_t* r, uint32_t a) {
    asm volatile("ldmatrix.sync.aligned.m8n8.x4.shared.b16 {%0,%1,%2,%3}, [%4];"
                 : "=r"(r[0]), "=r"(r[1]), "=r"(r[2]), "=r"(r[3]) : "r"(a));
}
__device__ __forceinline__ void ldmx4t(uint32_t* r, uint32_t a) {
    asm volatile("ldmatrix.sync.aligned.m8n8.x4.trans.shared.b16 {%0,%1,%2,%3}, [%4];"
                 : "=r"(r[0]), "=r"(r[1]), "=r"(r[2]), "=r"(r[3]) : "r"(a));
}
__device__ __forceinline__ void mma_f16(float* c, const uint32_t* a, uint32_t b0, uint32_t b1) {
    asm volatile("mma.sync.aligned.m16n8k16.row.col.f32.f16.f16.f32 "
                 "{%0,%1,%2,%3},{%4,%5,%6,%7},{%8,%9},{%0,%1,%2,%3};"
                 : "+f"(c[0]), "+f"(c[1]), "+f"(c[2]), "+f"(c[3])
                 : "r"(a[0]), "r"(a[1]), "r"(a[2]), "r"(a[3]), "r"(b0), "r"(b1));
}
__device__ __forceinline__ uint32_t h2_u32(__half2 h) {
    return *reinterpret_cast<uint32_t*>(&h);
}

// ======================= fused prep (x cvt + 4 weight transposes) ============
#define CVT_BLKS 8192                   // MTOT*DIM/4/256

__global__ void prep_kernel(
    const float* __restrict__ x,
    const float* __restrict__ Wq, const float* __restrict__ Wk,
    const float* __restrict__ Wv, const float* __restrict__ Wo,
    __half* __restrict__ Ah, __half* __restrict__ Oqkv, __half* __restrict__ Oo)
{
    __shared__ float t[32][33];
    int bx = blockIdx.x;
    if (bx < CVT_BLKS) {
        int i = bx * 256 + threadIdx.x;
        float4 v = *(const float4*)(x + 4 * (size_t)i);
        __half2 a = __floats2half2_rn(v.x, v.y);
        __half2 b = __floats2half2_rn(v.z, v.w);
        *(uint2*)(Ah + 4 * (size_t)i) = make_uint2(h2_u32(a), h2_u32(b));
        return;
    }
    int xb = (bx - CVT_BLKS) / 64;      // 0..159 column block
    int ky = (bx - CVT_BLKS) % 64;      // k block
    const float* W; __half* out; int N, row_off;
    if (xb < 64)       { W = Wq; out = Oqkv; N = DIM; row_off = 0;         }
    else if (xb < 80)  { W = Wk; out = Oqkv; N = KVD; row_off = DIM;       xb -= 64; }
    else if (xb < 96)  { W = Wv; out = Oqkv; N = KVD; row_off = DIM + KVD; xb -= 80; }
    else               { W = Wo; out = Oo;   N = DIM; row_off = 0;         xb -= 96; }
    int k0 = ky * 32, n0 = xb * 32;
    int tx = threadIdx.x & 31, ty = threadIdx.x >> 5;   // 32 x 8
    #pragma unroll
    for (int i = 0; i < 32; i += 8)
        t[ty + i][tx] = W[(size_t)(k0 + ty + i) * N + n0 + tx];
    __syncthreads();
    #pragma unroll
    for (int i = 0; i < 32; i += 8) {
        int n = n0 + ty + i, k = k0 + tx;
        out[(size_t)(n + row_off) * DIM + k] = __float2half_rn(t[tx][ty + i]);
    }
}

// ======================= fp16 mma.sync GEMM ==================================
// C = A[M,K] @ B[N,K]^T, K=2048. CTA 64x256, 256 threads, 8 warps (2m x 4n),
// warp tile 32x64, BK=32, 4-stage cp.async, 2 CTAs/SM.
// MODE 0: fp32 C out. MODE 1: fused QKV epilogue.
#define GSTRB 80                    // 64B data + 16B pad per row
#define ASUB  (64 * GSTRB)          // 5120
#define BSUB  (256 * GSTRB)         // 20480
#define GSTG  (ASUB + BSUB)         // 25600
#define GSMEM (4 * GSTG)            // 102400
#define GNIT  (DIM / 32)            // 64

template <int MODE>
__global__ __launch_bounds__(256, 2) void gemm_h_kernel(
    const __half* __restrict__ A, const __half* __restrict__ B,
    float* __restrict__ C, int Ntot,
    const float* __restrict__ cs, const float* __restrict__ sn,
    __half* __restrict__ Qh, __half* __restrict__ Kh, __half* __restrict__ Vh)
{
    extern __shared__ __align__(16) char smbuf[];
    const uint32_t smBase = smem_u32(smbuf);

    const int tid = threadIdx.x;
    const int lane = tid & 31;
    const int wid = tid >> 5;
    const int wm = wid >> 2, wn = wid & 3;     // 2m x 4n warps
    const int m0 = blockIdx.y * 64;
    const int n0 = blockIdx.x * 256;

    const uint32_t offA = ((((lane >> 3) & 1) * 8 + (lane & 7)) * GSTRB) + ((lane >> 4) * 16);
    const uint32_t offB = (((lane >> 4) * 8 + (lane & 7)) * GSTRB) + (((lane >> 3) & 1) * 16);

    const char* Ab = (const char*)A;
    const char* Bb = (const char*)B;

    auto load_stage = [&](int kc, int slot) {
        uint32_t base = smBase + slot * GSTG;
        int kb = kc * 64;
        {                                       // A: 256 chunks, 1/thread
            int row = tid >> 2, col = (tid & 3) * 16;
            cp16(base + row * GSTRB + col,
                 Ab + (size_t)(m0 + row) * WRB + kb + col);
        }
        #pragma unroll
        for (int j = 0; j < 4; j++) {           // B: 1024 chunks, 4/thread
            int c = tid + j * 256;
            int row = c >> 2, col = (c & 3) * 16;
            cp16(base + ASUB + row * GSTRB + col,
                 Bb + (size_t)(n0 + row) * WRB + kb + col);
        }
        cp_commit();
    };

    float acc[2][8][4];
    #pragma unroll
    for (int i = 0; i < 2; i++)
        #pragma unroll
        for (int j = 0; j < 8; j++)
            #pragma unroll
            for (int k = 0; k < 4; k++) acc[i][j][k] = 0.f;

    load_stage(0, 0);
    load_stage(1, 1);
    load_stage(2, 2);

    for (int i = 0; i < GNIT; i++) {
        if (i < GNIT - 2) cp_wait<2>();
        else if (i == GNIT - 2) cp_wait<1>();
        else cp_wait<0>();
        __syncthreads();
        if (i + 3 < GNIT) load_stage(i + 3, (i + 3) & 3);

        uint32_t sA = smBase + (i & 3) * GSTG;
        uint32_t sB = sA + ASUB;
        #pragma unroll
        for (int ks = 0; ks < 2; ks++) {
            uint32_t bfr[4][4];
            #pragma unroll
            for (int nt2 = 0; nt2 < 4; nt2++)
                ldmx4(bfr[nt2], sB + (wn * 64 + nt2 * 16) * GSTRB + ks * 32 + offB);
            uint32_t afr[2][4];
            #pragma unroll
            for (int mt = 0; mt < 2; mt++)
                ldmx4(afr[mt], sA + (wm * 32 + mt * 16) * GSTRB + ks * 32 + offA);
            #pragma unroll
            for (int mt = 0; mt < 2; mt++)
                #pragma unroll
                for (int nt = 0; nt < 8; nt++)
                    mma_f16(acc[mt][nt], afr[mt], bfr[nt >> 1][(nt & 1) * 2],
                            bfr[nt >> 1][(nt & 1) * 2 + 1]);
        }
    }

    #pragma unroll
    for (int mt = 0; mt < 2; mt++) {
        int r0 = m0 + wm * 32 + mt * 16 + (lane >> 2);
        int r1 = r0 + 8;
        int s0 = r0 & (SEQ - 1), s1 = r1 & (SEQ - 1);
        #pragma unroll
        for (int nt = 0; nt < 8; nt++) {
            float a0 = acc[mt][nt][0], a1 = acc[mt][nt][1];
            float a2 = acc[mt][nt][2], a3 = acc[mt][nt][3];
            int c = n0 + wn * 64 + nt * 8 + (lane & 3) * 2;
            if (MODE == 0) {
                *(float2*)(C + (size_t)r0 * Ntot + c) = make_float2(a0, a1);
                *(float2*)(C + (size_t)r1 * Ntot + c) = make_float2(a2, a3);
            } else {
                if (n0 < DIM) {               // Q: rope + scale
                    int fi = (c & 127) >> 1;
                    float c0 = cs[s0 * 64 + fi], z0 = sn[s0 * 64 + fi];
                    float c1 = cs[s1 * 64 + fi], z1 = sn[s1 * 64 + fi];
                    *(__half2*)(Qh + (size_t)r0 * DIM + c) =
                        __floats2half2_rn((a0 * c0 - a1 * z0) * QMUL, (a0 * z0 + a1 * c0) * QMUL);
                    *(__half2*)(Qh + (size_t)r1 * DIM + c) =
                        __floats2half2_rn((a2 * c1 - a3 * z1) * QMUL, (a2 * z1 + a3 * c1) * QMUL);
                } else if (n0 < DIM + KVD) {  // K: rope
                    int ck = c - DIM;
                    int fi = (ck & 127) >> 1;
                    float c0 = cs[s0 * 64 + fi], z0 = sn[s0 * 64 + fi];
                    float c1 = cs[s1 * 64 + fi], z1 = sn[s1 * 64 + fi];
                    *(__half2*)(Kh + (size_t)r0 * KVD + ck) =
                        __floats2half2_rn(a0 * c0 - a1 * z0, a0 * z0 + a1 * c0);
                    *(__half2*)(Kh + (size_t)r1 * KVD + ck) =
                        __floats2half2_rn(a2 * c1 - a3 * z1, a2 * z1 + a3 * c1);
                } else {                      // V: cvt
                    int cv = c - DIM - KVD;
                    *(__half2*)(Vh + (size_t)r0 * KVD + cv) = __floats2half2_rn(a0, a1);
                    *(__half2*)(Vh + (size_t)r1 * KVD + cv) = __floats2half2_rn(a2, a3);
                }
            }
        }
    }
}

// ---------------- Flash attention (fp16 mma.sync, BN=128) --------------------
// smem: K0 | K1 (double-buffered, 34.8KB each) | V (single, 34.8KB; Q aliased
// here initially). 104.4KB -> 2 CTAs/SM. 128 threads (4 warps, 16 q-rows each).
#define FSTR 272
#define KTILE (128 * FSTR)              // 34816
#define FSMEM (3 * KTILE)               // 104448

__global__ __launch_bounds__(128, 2) void flash_mma_kernel(
    const __half* __restrict__ Q, const __half* __restrict__ K,
    const __half* __restrict__ V, __half* __restrict__ Ah)
{
    extern __shared__ char fsm[];
    const uint32_t TK0 = smem_u32(fsm);
    const uint32_t TK1 = TK0 + KTILE;
    const uint32_t TV  = TK0 + 2 * KTILE;

    const int tid = threadIdx.x;
    const int lane = tid & 31;
    const int wid = tid >> 5;
    const int qtile = gridDim.x - 1 - blockIdx.x;   // heavy tiles first
    const int h = blockIdx.y, b = blockIdx.z;
    const int g = h >> 2;
    const int m_base = qtile * 64;
    const int niter = (qtile + 2) >> 1;             // 128-key iterations

    const uint32_t offQ = ((((lane >> 3) & 1) * 8 + (lane & 7)) * FSTR) + ((lane >> 4) * 16);
    const uint32_t offK = (((lane >> 4) * 8 + (lane & 7)) * FSTR) + (((lane >> 3) & 1) * 16);

    const char* Qb = (const char*)Q;
    const char* Kb = (const char*)K;
    const char* Vb = (const char*)V;

    auto load_k = [&](int nt) {
        uint32_t dst = (nt & 1) ? TK1 : TK0;
        #pragma unroll
        for (int it = 0; it < 16; it++) {
            int c = it * 128 + tid;
            int row = c >> 4, col = c & 15;
            cp16(dst + row * FSTR + col * 16,
                 Kb + ((size_t)(b * SEQ + nt * 128 + row) * KVD + g * HD) * 2 + col * 16);
        }
        cp_commit();
    };
    auto load_v = [&](int nt) {
        #pragma unroll
        for (int it = 0; it < 16; it++) {
            int c = it * 128 + tid;
            int row = c >> 4, col = c & 15;
            cp16(TV + row * FSTR + col * 16,
                 Vb + ((size_t)(b * SEQ + nt * 128 + row) * KVD + g * HD) * 2 + col * 16);
        }
        cp_commit();
    };

    // Q tile -> TV (aliased; overwritten by V after fragment extraction)
    #pragma unroll
    for (int it = 0; it < 8; it++) {
        int c = it * 128 + tid;
        int row = c >> 4, col = c & 15;
        cp16(TV + row * FSTR + col * 16,
             Qb + ((size_t)(b * SEQ + m_base + row) * DIM + h * HD) * 2 + col * 16);
    }
    cp_commit();
    load_k(0);
    cp_wait<1>();                         // Q ready; K(0) may be in flight
    __syncthreads();

    uint32_t qfr[8][4];
    #pragma unroll
    for (int kd = 0; kd < 8; kd++)
        ldmx4(qfr[kd], TV + (wid * 16) * FSTR + kd * 32 + offQ);

    float acc[16][4];
    #pragma unroll
    for (int i = 0; i < 16; i++)
        #pragma unroll
        for (int j = 0; j < 4; j++) acc[i][j] = 0.f;
    float mr0 = -1e30f, mr1 = -1e30f, l0 = 0.f, l1 = 0.f;

    for (int nt = 0; nt < niter; nt++) {
        cp_wait<0>();                     // K(nt) resident; prior PV/qfr done
        __syncthreads();
        load_v(nt);                       // overwrites TV (safe after sync)
        bool haveNext = (nt + 1 < niter);
        if (haveNext) load_k(nt + 1);

        uint32_t smK = (nt & 1) ? TK1 : TK0;

        // S = Q @ K^T over 128 keys
        float s[16][4];
        #pragma unroll
        for (int i = 0; i < 16; i++)
            #pragma unroll
            for (int j = 0; j < 4; j++) s[i][j] = 0.f;
        #pragma unroll
        for (int kd = 0; kd < 8; kd++) {
            #pragma unroll
            for (int nt2 = 0; nt2 < 8; nt2++) {
                uint32_t bfr[4];
                ldmx4(bfr, smK + nt2 * 16 * FSTR + kd * 32 + offK);
                mma_f16(s[2 * nt2],     qfr[kd], bfr[0], bfr[1]);
                mma_f16(s[2 * nt2 + 1], qfr[kd], bfr[2], bfr[3]);
            }
        }

        if (nt == niter - 1) {            // causal mask (global indices)
            int rl0 = m_base + wid * 16 + (lane >> 2);
            int rl1 = rl0 + 8;
            #pragma unroll
            for (int kt = 0; kt < 16; kt++) {
                int cl = nt * 128 + kt * 8 + (lane & 3) * 2;
                if (cl     > rl0) s[kt][0] = -1e30f;
                if (cl + 1 > rl0) s[kt][1] = -1e30f;
                if (cl     > rl1) s[kt][2] = -1e30f;
                if (cl + 1 > rl1) s[kt][3] = -1e30f;
            }
        }

        float t0 = -1e30f, t1 = -1e30f;
        #pragma unroll
        for (int kt = 0; kt < 16; kt++) {
            t0 = fmaxf(t0, fmaxf(s[kt][0], s[kt][1]));
            t1 = fmaxf(t1, fmaxf(s[kt][2], s[kt][3]));
        }
        t0 = fmaxf(t0, __shfl_xor_sync(0xffffffffu, t0, 1));
        t0 = fmaxf(t0, __shfl_xor_sync(0xffffffffu, t0, 2));
        t1 = fmaxf(t1, __shfl_xor_sync(0xffffffffu, t1, 1));
        t1 = fmaxf(t1, __shfl_xor_sync(0xffffffffu, t1, 2));

        float mn0 = fmaxf(mr0, t0), mn1 = fmaxf(mr1, t1);
        float a0 = exp2f(mr0 - mn0), a1 = exp2f(mr1 - mn1);
        mr0 = mn0; mr1 = mn1;

        uint32_t pa[16][2];
        float lt0 = 0.f, lt1 = 0.f;
        #pragma unroll
        for (int kt = 0; kt < 16; kt++) {
            __half2 hp0 = h2exp2(__floats2half2_rn(s[kt][0] - mn0, s[kt][1] - mn0));
            __half2 hp1 = h2exp2(__floats2half2_rn(s[kt][2] - mn1, s[kt][3] - mn1));
            pa[kt][0] = h2_u32(hp0);
            pa[kt][1] = h2_u32(hp1);
            float2 f0 = __half22float2(hp0);
            float2 f1 = __half22float2(hp1);
            lt0 += f0.x + f0.y;
            lt1 += f1.x + f1.y;
        }
        lt0 += __shfl_xor_sync(0xffffffffu, lt0, 1);
        lt0 += __shfl_xor_sync(0xffffffffu, lt0, 2);
        lt1 += __shfl_xor_sync(0xffffffffu, lt1, 1);
        lt1 += __shfl_xor_sync(0xffffffffu, lt1, 2);
        l0 = l0 * a0 + lt0;
        l1 = l1 * a1 + lt1;

        // rescale accumulators (warp-uniform skip when all alphas == 1)
        if (!__all_sync(0xffffffffu, (a0 == 1.f) & (a1 == 1.f))) {
            #pragma unroll
            for (int i = 0; i < 16; i++) {
                acc[i][0] *= a0; acc[i][1] *= a0;
                acc[i][2] *= a1; acc[i][3] *= a1;
            }
        }

        if (haveNext) cp_wait<1>();       // V(nt) done; K(nt+1) may be pending
        else cp_wait<0>();
        __syncthreads();

        // O += P @ V  (k-dim = 128 keys)
        #pragma unroll
        for (int kt2 = 0; kt2 < 8; kt2++) {
            uint32_t pfr[4] = { pa[2 * kt2][0], pa[2 * kt2][1],
                                pa[2 * kt2 + 1][0], pa[2 * kt2 + 1][1] };
            #pragma unroll
            for (int dp = 0; dp < 8; dp++) {
                uint32_t vfr[4];
                ldmx4t(vfr, TV + kt2 * 16 * FSTR + dp * 32 + offQ);
                mma_f16(acc[2 * dp],     pfr, vfr[0], vfr[1]);
                mma_f16(acc[2 * dp + 1], pfr, vfr[2], vfr[3]);
            }
        }
    }

    // epilogue: normalize + plain fp16 into Ah [token, DIM]
    float inv0 = 1.f / l0, inv1 = 1.f / l1;
    int r0 = b * SEQ + m_base + wid * 16 + (lane >> 2);
    int r1 = r0 + 8;
    #pragma unroll
    for (int ntl = 0; ntl < 16; ntl++) {
        int c = h * HD + ntl * 8 + (lane & 3) * 2;
        *(__half2*)(Ah + (size_t)r0 * DIM + c) =
            __floats2half2_rn(acc[ntl][0] * inv0, acc[ntl][1] * inv0);
        *(__half2*)(Ah + (size_t)r1 * DIM + c) =
            __floats2half2_rn(acc[ntl][2] * inv1, acc[ntl][3] * inv1);
    }
}

// ---------------- launch -----------------------------------------------------
extern "C" void kernel_launch(void* const* d_in, const int* in_sizes, int n_in,
                              void* d_out, int out_size)
{
    const float* x  = (const float*)d_in[0];
    const float* fc = (const float*)d_in[1];
    const float* fs = (const float*)d_in[2];
    const float* Wq = (const float*)d_in[3];
    const float* Wk = (const float*)d_in[4];
    const float* Wv = (const float*)d_in[5];
    const float* Wo = (const float*)d_in[6];
    float* out = (float*)d_out;

    __half *Ah, *Wqkv, *Wo2, *Qh, *Kh, *Vh;
    cudaGetSymbolAddress((void**)&Ah,   g_Ah);
    cudaGetSymbolAddress((void**)&Wqkv, g_Wqkv);
    cudaGetSymbolAddress((void**)&Wo2,  g_Wo2);
    cudaGetSymbolAddress((void**)&Qh,   g_Qh);
    cudaGetSymbolAddress((void**)&Kh,   g_Kh);
    cudaGetSymbolAddress((void**)&Vh,   g_Vh);

    cudaFuncSetAttribute((const void*)gemm_h_kernel<0>,
                         cudaFuncAttributeMaxDynamicSharedMemorySize, GSMEM);
    cudaFuncSetAttribute((const void*)gemm_h_kernel<1>,
                         cudaFuncAttributeMaxDynamicSharedMemorySize, GSMEM);
    cudaFuncSetAttribute(flash_mma_kernel, cudaFuncAttributeMaxDynamicSharedMemorySize, FSMEM);

    // fused conversions (1 launch)
    prep_kernel<<<CVT_BLKS + 160 * 64, 256>>>(x, Wq, Wk, Wv, Wo, Ah, Wqkv, Wo2);

    // fused QKV projection + RoPE + fp16 convert
    gemm_h_kernel<1><<<dim3(NQKV / 256, MTOT / 64), 256, GSMEM>>>(
        Ah, Wqkv, nullptr, 0, fc, fs, Qh, Kh, Vh);

    // flash attention -> Ah fp16
    flash_mma_kernel<<<dim3(SEQ / 64, NH, BATCH), 128, FSMEM>>>(Qh, Kh, Vh, Ah);

    // output projection
    gemm_h_kernel<0><<<dim3(DIM / 256, MTOT / 64), 256, GSMEM>>>(
        Ah, Wo2, out, DIM, nullptr, nullptr, nullptr, nullptr, nullptr);
}

// round 14
// speedup vs baseline: 1.5398x; 1.5398x over previous
#include <cuda_runtime.h>
#include <cuda_bf16.h>
#include <cuda_fp16.h>
#include <math.h>
#include <stdint.h>

#define BATCH 2
#define SEQ 2048
#define DIM 2048
#define NH 16
#define NKV 4
#define HD 128
#define MTOT (BATCH * SEQ)          // 4096
#define KVD (NKV * HD)              // 512
#define NQKV (DIM + 2 * KVD)        // 3072
#define WRB (DIM * 2)               // row bytes for fp16 [*, K=2048]

// ---------------- scratch (static device globals) ----------------------------
__device__ __half g_Ah  [(size_t)MTOT * DIM];   // activations fp16 (x, then attn out)
__device__ __half g_Wqkv[(size_t)NQKV * DIM];   // [WqT;WkT;WvT] fp16 [N,K]
__device__ __half g_Wo2 [(size_t)DIM  * DIM];   // WoT fp16
__device__ __half g_Qh  [(size_t)MTOT * DIM];
__device__ __half g_Kh  [(size_t)MTOT * KVD];
__device__ __half g_Vh  [(size_t)MTOT * KVD];

#define QMUL (0.08838834764831845f * 1.4426950408889634f)   // scale * log2(e)

// ======================= small PTX helpers ===================================
__device__ __forceinline__ uint32_t smem_u32(const void* p) {
    uint32_t a;
    asm("{ .reg .u64 t; cvta.to.shared.u64 t, %1; cvt.u32.u64 %0, t; }" : "=r"(a) : "l"(p));
    return a;
}
__device__ __forceinline__ void cp16(uint32_t dst, const void* src) {
    asm volatile("cp.async.cg.shared.global [%0], [%1], 16;" :: "r"(dst), "l"(src));
}
__device__ __forceinline__ void cp_commit() { asm volatile("cp.async.commit_group;"); }
template <int N> __device__ __forceinline__ void cp_wait() {
    asm volatile("cp.async.wait_group %0;" :: "n"(N));
}
__device__ __forceinline__ void ldmx4(uint32_t* r, uint32_t a) {
    asm volatile("ldmatrix.sync.aligned.m8n8.x4.shared.b16 {%0,%1,%2,%3}, [%4];"
                 : "=r"(r[0]), "=r"(r[1]), "=r"(r[2]), "=r"(r[3]) : "r"(a));
}
__device__ __forceinline__ void ldmx4t(uint32_t* r, uint32_t a) {
    asm volatile("ldmatrix.sync.aligned.m8n8.x4.trans.shared.b16 {%0,%1,%2,%3}, [%4];"
                 : "=r"(r[0]), "=r"(r[1]), "=r"(r[2]), "=r"(r[3]) : "r"(a));
}
__device__ __forceinline__ void mma_f16(float* c, const uint32_t* a, uint32_t b0, uint32_t b1) {
    asm volatile("mma.sync.aligned.m16n8k16.row.col.f32.f16.f16.f32 "
                 "{%0,%1,%2,%3},{%4,%5,%6,%7},{%8,%9},{%0,%1,%2,%3};"
                 : "+f"(c[0]), "+f"(c[1]), "+f"(c[2]), "+f"(c[3])
                 : "r"(a[0]), "r"(a[1]), "r"(a[2]), "r"(a[3]), "r"(b0), "r"(b1));
}
__device__ __forceinline__ uint32_t h2_u32(__half2 h) {
    return *reinterpret_cast<uint32_t*>(&h);
}

// ======================= fused prep (x cvt + 4 weight transposes) ============
#define CVT_BLKS 8192                   // MTOT*DIM/4/256

__global__ void prep_kernel(
    const float* __restrict__ x,
    const float* __restrict__ Wq, const float* __restrict__ Wk,
    const float* __restrict__ Wv, const float* __restrict__ Wo,
    __half* __restrict__ Ah, __half* __restrict__ Oqkv, __half* __restrict__ Oo)
{
    __shared__ float t[32][33];
    int bx = blockIdx.x;
    if (bx < CVT_BLKS) {
        int i = bx * 256 + threadIdx.x;
        float4 v = *(const float4*)(x + 4 * (size_t)i);
        __half2 a = __floats2half2_rn(v.x, v.y);
        __half2 b = __floats2half2_rn(v.z, v.w);
        *(uint2*)(Ah + 4 * (size_t)i) = make_uint2(h2_u32(a), h2_u32(b));
        return;
    }
    int xb = (bx - CVT_BLKS) / 64;      // 0..159 column block
    int ky = (bx - CVT_BLKS) % 64;      // k block
    const float* W; __half* out; int N, row_off;
    if (xb < 64)       { W = Wq; out = Oqkv; N = DIM; row_off = 0;         }
    else if (xb < 80)  { W = Wk; out = Oqkv; N = KVD; row_off = DIM;       xb -= 64; }
    else if (xb < 96)  { W = Wv; out = Oqkv; N = KVD; row_off = DIM + KVD; xb -= 80; }
    else               { W = Wo; out = Oo;   N = DIM; row_off = 0;         xb -= 96; }
    int k0 = ky * 32, n0 = xb * 32;
    int tx = threadIdx.x & 31, ty = threadIdx.x >> 5;   // 32 x 8
    #pragma unroll
    for (int i = 0; i < 32; i += 8)
        t[ty + i][tx] = W[(size_t)(k0 + ty + i) * N + n0 + tx];
    __syncthreads();
    #pragma unroll
    for (int i = 0; i < 32; i += 8) {
        int n = n0 + ty + i, k = k0 + tx;
        out[(size_t)(n + row_off) * DIM + k] = __float2half_rn(t[tx][ty + i]);
    }
}

// ======================= fp16 mma.sync GEMM ==================================
// C = A[M,K] @ B[N,K]^T, K=2048. CTA 128x256, 512 threads, 16 warps (4m x 4n),
// warp tile 32x64, BK=64, 3-stage cp.async (barrier every 64-K chunk).
// MODE 0: fp32 C out. MODE 1: fused QKV epilogue.
#define GSTRB 144                   // 128B data + 16B pad per row
#define ASUB  (128 * GSTRB)         // 18432
#define GSTG  (384 * GSTRB)         // 55296 (A 128 rows + B 256 rows)
#define GSMEM (3 * GSTG)            // 165888
#define GNIT  (DIM / 64)            // 32

template <int MODE>
__global__ __launch_bounds__(512) void gemm_h_kernel(
    const __half* __restrict__ A, const __half* __restrict__ B,
    float* __restrict__ C, int Ntot,
    const float* __restrict__ cs, const float* __restrict__ sn,
    __half* __restrict__ Qh, __half* __restrict__ Kh, __half* __restrict__ Vh)
{
    extern __shared__ __align__(16) char smbuf[];
    const uint32_t smBase = smem_u32(smbuf);

    const int tid = threadIdx.x;
    const int lane = tid & 31;
    const int wid = tid >> 5;
    const int wm = wid >> 2, wn = wid & 3;     // 4m x 4n warps
    const int m0 = blockIdx.y * 128;
    const int n0 = blockIdx.x * 256;

    const uint32_t offA = ((((lane >> 3) & 1) * 8 + (lane & 7)) * GSTRB) + ((lane >> 4) * 16);
    const uint32_t offB = (((lane >> 4) * 8 + (lane & 7)) * GSTRB) + (((lane >> 3) & 1) * 16);

    const char* Ab = (const char*)A;
    const char* Bb = (const char*)B;

    auto load_stage = [&](int kc, int slot) {
        uint32_t base = smBase + slot * GSTG;
        int kb = kc * 128;                      // 64 fp16 = 128 bytes per chunk
        #pragma unroll
        for (int j = 0; j < 2; j++) {           // A: 128 rows x 8 chunks = 1024
            int c = tid + j * 512;
            int row = c >> 3, col = (c & 7) * 16;
            cp16(base + row * GSTRB + col,
                 Ab + (size_t)(m0 + row) * WRB + kb + col);
        }
        #pragma unroll
        for (int j = 0; j < 4; j++) {           // B: 256 rows x 8 chunks = 2048
            int c = tid + j * 512;
            int row = c >> 3, col = (c & 7) * 16;
            cp16(base + ASUB + row * GSTRB + col,
                 Bb + (size_t)(n0 + row) * WRB + kb + col);
        }
        cp_commit();
    };

    float acc[2][8][4];
    #pragma unroll
    for (int i = 0; i < 2; i++)
        #pragma unroll
        for (int j = 0; j < 8; j++)
            #pragma unroll
            for (int k = 0; k < 4; k++) acc[i][j][k] = 0.f;

    load_stage(0, 0);
    load_stage(1, 1);

    for (int i = 0; i < GNIT; i++) {
        if (i + 2 < GNIT) { load_stage(i + 2, (i + 2) % 3); cp_wait<2>(); }
        else if (i + 2 == GNIT) cp_wait<1>();
        else cp_wait<0>();
        __syncthreads();

        uint32_t sA = smBase + (i % 3) * GSTG;
        uint32_t sB = sA + ASUB;
        #pragma unroll
        for (int ks = 0; ks < 4; ks++) {
            uint32_t bfr[4][4];
            #pragma unroll
            for (int nt2 = 0; nt2 < 4; nt2++)
                ldmx4(bfr[nt2], sB + (wn * 64 + nt2 * 16) * GSTRB + ks * 32 + offB);
            uint32_t afr[2][4];
            #pragma unroll
            for (int mt = 0; mt < 2; mt++)
                ldmx4(afr[mt], sA + (wm * 32 + mt * 16) * GSTRB + ks * 32 + offA);
            #pragma unroll
            for (int mt = 0; mt < 2; mt++)
                #pragma unroll
                for (int nt = 0; nt < 8; nt++)
                    mma_f16(acc[mt][nt], afr[mt], bfr[nt >> 1][(nt & 1) * 2],
                            bfr[nt >> 1][(nt & 1) * 2 + 1]);
        }
        __syncthreads();
    }

    #pragma unroll
    for (int mt = 0; mt < 2; mt++) {
        int r0 = m0 + wm * 32 + mt * 16 + (lane >> 2);
        int r1 = r0 + 8;
        int s0 = r0 & (SEQ - 1), s1 = r1 & (SEQ - 1);
        #pragma unroll
        for (int nt = 0; nt < 8; nt++) {
            float a0 = acc[mt][nt][0], a1 = acc[mt][nt][1];
            float a2 = acc[mt][nt][2], a3 = acc[mt][nt][3];
            int c = n0 + wn * 64 + nt * 8 + (lane & 3) * 2;
            if (MODE == 0) {
                *(float2*)(C + (size_t)r0 * Ntot + c) = make_float2(a0, a1);
                *(float2*)(C + (size_t)r1 * Ntot + c) = make_float2(a2, a3);
            } else {
                if (n0 < DIM) {               // Q: rope + scale
                    int fi = (c & 127) >> 1;
                    float c0 = cs[s0 * 64 + fi], z0 = sn[s0 * 64 + fi];
                    float c1 = cs[s1 * 64 + fi], z1 = sn[s1 * 64 + fi];
                    *(__half2*)(Qh + (size_t)r0 * DIM + c) =
                        __floats2half2_rn((a0 * c0 - a1 * z0) * QMUL, (a0 * z0 + a1 * c0) * QMUL);
                    *(__half2*)(Qh + (size_t)r1 * DIM + c) =
                        __floats2half2_rn((a2 * c1 - a3 * z1) * QMUL, (a2 * z1 + a3 * c1) * QMUL);
                } else if (n0 < DIM + KVD) {  // K: rope
                    int ck = c - DIM;
                    int fi = (ck & 127) >> 1;
                    float c0 = cs[s0 * 64 + fi], z0 = sn[s0 * 64 + fi];
                    float c1 = cs[s1 * 64 + fi], z1 = sn[s1 * 64 + fi];
                    *(__half2*)(Kh + (size_t)r0 * KVD + ck) =
                        __floats2half2_rn(a0 * c0 - a1 * z0, a0 * z0 + a1 * c0);
                    *(__half2*)(Kh + (size_t)r1 * KVD + ck) =
                        __floats2half2_rn(a2 * c1 - a3 * z1, a2 * z1 + a3 * c1);
                } else {                      // V: cvt
                    int cv = c - DIM - KVD;
                    *(__half2*)(Vh + (size_t)r0 * KVD + cv) = __floats2half2_rn(a0, a1);
                    *(__half2*)(Vh + (size_t)r1 * KVD + cv) = __floats2half2_rn(a2, a3);
                }
            }
        }
    }
}

// ---------------- Flash attention (fp16 mma.sync, BN=128) --------------------
// smem: K0 | K1 (double-buffered, 34.8KB each) | V (single, 34.8KB; Q aliased
// here initially). 104.4KB -> 2 CTAs/SM. 128 threads (4 warps, 16 q-rows each).
#define FSTR 272
#define KTILE (128 * FSTR)              // 34816
#define FSMEM (3 * KTILE)               // 104448

__global__ __launch_bounds__(128, 2) void flash_mma_kernel(
    const __half* __restrict__ Q, const __half* __restrict__ K,
    const __half* __restrict__ V, __half* __restrict__ Ah)
{
    extern __shared__ char fsm[];
    const uint32_t TK0 = smem_u32(fsm);
    const uint32_t TK1 = TK0 + KTILE;
    const uint32_t TV  = TK0 + 2 * KTILE;

    const int tid = threadIdx.x;
    const int lane = tid & 31;
    const int wid = tid >> 5;
    const int qtile = gridDim.x - 1 - blockIdx.x;   // heavy tiles first
    const int h = blockIdx.y, b = blockIdx.z;
    const int g = h >> 2;
    const int m_base = qtile * 64;
    const int niter = (qtile + 2) >> 1;             // 128-key iterations

    const uint32_t offQ = ((((lane >> 3) & 1) * 8 + (lane & 7)) * FSTR) + ((lane >> 4) * 16);
    const uint32_t offK = (((lane >> 4) * 8 + (lane & 7)) * FSTR) + (((lane >> 3) & 1) * 16);

    const char* Qb = (const char*)Q;
    const char* Kb = (const char*)K;
    const char* Vb = (const char*)V;

    auto load_k = [&](int nt) {
        uint32_t dst = (nt & 1) ? TK1 : TK0;
        #pragma unroll
        for (int it = 0; it < 16; it++) {
            int c = it * 128 + tid;
            int row = c >> 4, col = c & 15;
            cp16(dst + row * FSTR + col * 16,
                 Kb + ((size_t)(b * SEQ + nt * 128 + row) * KVD + g * HD) * 2 + col * 16);
        }
        cp_commit();
    };
    auto load_v = [&](int nt) {
        #pragma unroll
        for (int it = 0; it < 16; it++) {
            int c = it * 128 + tid;
            int row = c >> 4, col = c & 15;
            cp16(TV + row * FSTR + col * 16,
                 Vb + ((size_t)(b * SEQ + nt * 128 + row) * KVD + g * HD) * 2 + col * 16);
        }
        cp_commit();
    };

    // Q tile -> TV (aliased; overwritten by V after fragment extraction)
    #pragma unroll
    for (int it = 0; it < 8; it++) {
        int c = it * 128 + tid;
        int row = c >> 4, col = c & 15;
        cp16(TV + row * FSTR + col * 16,
             Qb + ((size_t)(b * SEQ + m_base + row) * DIM + h * HD) * 2 + col * 16);
    }
    cp_commit();
    load_k(0);
    cp_wait<1>();                         // Q ready; K(0) may be in flight
    __syncthreads();

    uint32_t qfr[8][4];
    #pragma unroll
    for (int kd = 0; kd < 8; kd++)
        ldmx4(qfr[kd], TV + (wid * 16) * FSTR + kd * 32 + offQ);

    float acc[16][4];
    #pragma unroll
    for (int i = 0; i < 16; i++)
        #pragma unroll
        for (int j = 0; j < 4; j++) acc[i][j] = 0.f;
    float mr0 = -1e30f, mr1 = -1e30f, l0 = 0.f, l1 = 0.f;

    for (int nt = 0; nt < niter; nt++) {
        cp_wait<0>();                     // K(nt) resident; prior PV/qfr done
        __syncthreads();
        load_v(nt);                       // overwrites TV (safe after sync)
        bool haveNext = (nt + 1 < niter);
        if (haveNext) load_k(nt + 1);

        uint32_t smK = (nt & 1) ? TK1 : TK0;

        // S = Q @ K^T over 128 keys
        float s[16][4];
        #pragma unroll
        for (int i = 0; i < 16; i++)
            #pragma unroll
            for (int j = 0; j < 4; j++) s[i][j] = 0.f;
        #pragma unroll
        for (int kd = 0; kd < 8; kd++) {
            #pragma unroll
            for (int nt2 = 0; nt2 < 8; nt2++) {
                uint32_t bfr[4];
                ldmx4(bfr, smK + nt2 * 16 * FSTR + kd * 32 + offK);
                mma_f16(s[2 * nt2],     qfr[kd], bfr[0], bfr[1]);
                mma_f16(s[2 * nt2 + 1], qfr[kd], bfr[2], bfr[3]);
            }
        }

        if (nt == niter - 1) {            // causal mask (global indices)
            int rl0 = m_base + wid * 16 + (lane >> 2);
            int rl1 = rl0 + 8;
            #pragma unroll
            for (int kt = 0; kt < 16; kt++) {
                int cl = nt * 128 + kt * 8 + (lane & 3) * 2;
                if (cl     > rl0) s[kt][0] = -1e30f;
                if (cl + 1 > rl0) s[kt][1] = -1e30f;
                if (cl     > rl1) s[kt][2] = -1e30f;
                if (cl + 1 > rl1) s[kt][3] = -1e30f;
            }
        }

        float t0 = -1e30f, t1 = -1e30f;
        #pragma unroll
        for (int kt = 0; kt < 16; kt++) {
            t0 = fmaxf(t0, fmaxf(s[kt][0], s[kt][1]));
            t1 = fmaxf(t1, fmaxf(s[kt][2], s[kt][3]));
        }
        t0 = fmaxf(t0, __shfl_xor_sync(0xffffffffu, t0, 1));
        t0 = fmaxf(t0, __shfl_xor_sync(0xffffffffu, t0, 2));
        t1 = fmaxf(t1, __shfl_xor_sync(0xffffffffu, t1, 1));
        t1 = fmaxf(t1, __shfl_xor_sync(0xffffffffu, t1, 2));

        float mn0 = fmaxf(mr0, t0), mn1 = fmaxf(mr1, t1);
        float a0 = exp2f(mr0 - mn0), a1 = exp2f(mr1 - mn1);
        mr0 = mn0; mr1 = mn1;

        uint32_t pa[16][2];
        float lt0 = 0.f, lt1 = 0.f;
        #pragma unroll
        for (int kt = 0; kt < 16; kt++) {
            __half2 hp0 = h2exp2(__floats2half2_rn(s[kt][0] - mn0, s[kt][1] - mn0));
            __half2 hp1 = h2exp2(__floats2half2_rn(s[kt][2] - mn1, s[kt][3] - mn1));
            pa[kt][0] = h2_u32(hp0);
            pa[kt][1] = h2_u32(hp1);
            float2 f0 = __half22float2(hp0);
            float2 f1 = __half22float2(hp1);
            lt0 += f0.x + f0.y;
            lt1 += f1.x + f1.y;
        }
        lt0 += __shfl_xor_sync(0xffffffffu, lt0, 1);
        lt0 += __shfl_xor_sync(0xffffffffu, lt0, 2);
        lt1 += __shfl_xor_sync(0xffffffffu, lt1, 1);
        lt1 += __shfl_xor_sync(0xffffffffu, lt1, 2);
        l0 = l0 * a0 + lt0;
        l1 = l1 * a1 + lt1;

        // rescale accumulators (warp-uniform skip when all alphas == 1)
        if (!__all_sync(0xffffffffu, (a0 == 1.f) & (a1 == 1.f))) {
            #pragma unroll
            for (int i = 0; i < 16; i++) {
                acc[i][0] *= a0; acc[i][1] *= a0;
                acc[i][2] *= a1; acc[i][3] *= a1;
            }
        }

        if (haveNext) cp_wait<1>();       // V(nt) done; K(nt+1) may be pending
        else cp_wait<0>();
        __syncthreads();

        // O += P @ V  (k-dim = 128 keys)
        #pragma unroll
        for (int kt2 = 0; kt2 < 8; kt2++) {
            uint32_t pfr[4] = { pa[2 * kt2][0], pa[2 * kt2][1],
                                pa[2 * kt2 + 1][0], pa[2 * kt2 + 1][1] };
            #pragma unroll
            for (int dp = 0; dp < 8; dp++) {
                uint32_t vfr[4];
                ldmx4t(vfr, TV + kt2 * 16 * FSTR + dp * 32 + offQ);
                mma_f16(acc[2 * dp],     pfr, vfr[0], vfr[1]);
                mma_f16(acc[2 * dp + 1], pfr, vfr[2], vfr[3]);
            }
        }
    }

    // epilogue: normalize + plain fp16 into Ah [token, DIM]
    float inv0 = 1.f / l0, inv1 = 1.f / l1;
    int r0 = b * SEQ + m_base + wid * 16 + (lane >> 2);
    int r1 = r0 + 8;
    #pragma unroll
    for (int ntl = 0; ntl < 16; ntl++) {
        int c = h * HD + ntl * 8 + (lane & 3) * 2;
        *(__half2*)(Ah + (size_t)r0 * DIM + c) =
            __floats2half2_rn(acc[ntl][0] * inv0, acc[ntl][1] * inv0);
        *(__half2*)(Ah + (size_t)r1 * DIM + c) =
            __floats2half2_rn(acc[ntl][2] * inv1, acc[ntl][3] * inv1);
    }
}

// ---------------- launch -----------------------------------------------------
extern "C" void kernel_launch(void* const* d_in, const int* in_sizes, int n_in,
                              void* d_out, int out_size)
{
    const float* x  = (const float*)d_in[0];
    const float* fc = (const float*)d_in[1];
    const float* fs = (const float*)d_in[2];
    const float* Wq = (const float*)d_in[3];
    const float* Wk = (const float*)d_in[4];
    const float* Wv = (const float*)d_in[5];
    const float* Wo = (const float*)d_in[6];
    float* out = (float*)d_out;

    __half *Ah, *Wqkv, *Wo2, *Qh, *Kh, *Vh;
    cudaGetSymbolAddress((void**)&Ah,   g_Ah);
    cudaGetSymbolAddress((void**)&Wqkv, g_Wqkv);
    cudaGetSymbolAddress((void**)&Wo2,  g_Wo2);
    cudaGetSymbolAddress((void**)&Qh,   g_Qh);
    cudaGetSymbolAddress((void**)&Kh,   g_Kh);
    cudaGetSymbolAddress((void**)&Vh,   g_Vh);

    cudaFuncSetAttribute((const void*)gemm_h_kernel<0>,
                         cudaFuncAttributeMaxDynamicSharedMemorySize, GSMEM);
    cudaFuncSetAttribute((const void*)gemm_h_kernel<1>,
                         cudaFuncAttributeMaxDynamicSharedMemorySize, GSMEM);
    cudaFuncSetAttribute(flash_mma_kernel, cudaFuncAttributeMaxDynamicSharedMemorySize, FSMEM);

    // fused conversions (1 launch)
    prep_kernel<<<CVT_BLKS + 160 * 64, 256>>>(x, Wq, Wk, Wv, Wo, Ah, Wqkv, Wo2);

    // fused QKV projection + RoPE + fp16 convert
    gemm_h_kernel<1><<<dim3(NQKV / 256, MTOT / 128), 512, GSMEM>>>(
        Ah, Wqkv, nullptr, 0, fc, fs, Qh, Kh, Vh);

    // flash attention -> Ah fp16
    flash_mma_kernel<<<dim3(SEQ / 64, NH, BATCH), 128, FSMEM>>>(Qh, Kh, Vh, Ah);

    // output projection
    gemm_h_kernel<0><<<dim3(DIM / 256, MTOT / 128), 512, GSMEM>>>(
        Ah, Wo2, out, DIM, nullptr, nullptr, nullptr, nullptr, nullptr);
}

// round 15
// speedup vs baseline: 1.6733x; 1.0867x over previous
#include <cuda_runtime.h>
#include <cuda_bf16.h>
#include <cuda_fp16.h>
#include <math.h>
#include <stdint.h>

#define BATCH 2
#define SEQ 2048
#define DIM 2048
#define NH 16
#define NKV 4
#define HD 128
#define MTOT (BATCH * SEQ)          // 4096
#define KVD (NKV * HD)              // 512
#define NQKV (DIM + 2 * KVD)        // 3072
#define WRB (DIM * 2)               // row bytes for fp16 [*, K=2048]

// ---------------- scratch (static device globals) ----------------------------
__device__ __half g_Ah  [(size_t)MTOT * DIM];   // activations fp16 (x, then attn out)
__device__ __half g_Wqkv[(size_t)NQKV * DIM];   // [WqT;WkT;WvT] fp16 [N,K]
__device__ __half g_Wo2 [(size_t)DIM  * DIM];   // WoT fp16
__device__ __half g_Qh  [(size_t)MTOT * DIM];
__device__ __half g_Kh  [(size_t)MTOT * KVD];
__device__ __half g_Vh  [(size_t)MTOT * KVD];

#define QMUL (0.08838834764831845f * 1.4426950408889634f)   // scale * log2(e)

// ======================= small PTX helpers ===================================
__device__ __forceinline__ uint32_t smem_u32(const void* p) {
    uint32_t a;
    asm("{ .reg .u64 t; cvta.to.shared.u64 t, %1; cvt.u32.u64 %0, t; }" : "=r"(a) : "l"(p));
    return a;
}
__device__ __forceinline__ void cp16(uint32_t dst, const void* src) {
    asm volatile("cp.async.cg.shared.global [%0], [%1], 16;" :: "r"(dst), "l"(src));
}
__device__ __forceinline__ void cp_commit() { asm volatile("cp.async.commit_group;"); }
template <int N> __device__ __forceinline__ void cp_wait() {
    asm volatile("cp.async.wait_group %0;" :: "n"(N));
}
__device__ __forceinline__ void ldmx4(uint32_t* r, uint32_t a) {
    asm volatile("ldmatrix.sync.aligned.m8n8.x4.shared.b16 {%0,%1,%2,%3}, [%4];"
                 : "=r"(r[0]), "=r"(r[1]), "=r"(r[2]), "=r"(r[3]) : "r"(a));
}
__device__ __forceinline__ void ldmx4t(uint32_t* r, uint32_t a) {
    asm volatile("ldmatrix.sync.aligned.m8n8.x4.trans.shared.b16 {%0,%1,%2,%3}, [%4];"
                 : "=r"(r[0]), "=r"(r[1]), "=r"(r[2]), "=r"(r[3]) : "r"(a));
}
__device__ __forceinline__ void mma_f16(float* c, const uint32_t* a, uint32_t b0, uint32_t b1) {
    asm volatile("mma.sync.aligned.m16n8k16.row.col.f32.f16.f16.f32 "
                 "{%0,%1,%2,%3},{%4,%5,%6,%7},{%8,%9},{%0,%1,%2,%3};"
                 : "+f"(c[0]), "+f"(c[1]), "+f"(c[2]), "+f"(c[3])
                 : "r"(a[0]), "r"(a[1]), "r"(a[2]), "r"(a[3]), "r"(b0), "r"(b1));
}
__device__ __forceinline__ uint32_t h2_u32(__half2 h) {
    return *reinterpret_cast<uint32_t*>(&h);
}

// ======================= fused prep (x cvt + 4 weight transposes) ============
#define CVT_BLKS 8192                   // MTOT*DIM/4/256

__global__ void prep_kernel(
    const float* __restrict__ x,
    const float* __restrict__ Wq, const float* __restrict__ Wk,
    const float* __restrict__ Wv, const float* __restrict__ Wo,
    __half* __restrict__ Ah, __half* __restrict__ Oqkv, __half* __restrict__ Oo)
{
    __shared__ float t[32][33];
    int bx = blockIdx.x;
    if (bx < CVT_BLKS) {
        int i = bx * 256 + threadIdx.x;
        float4 v = *(const float4*)(x + 4 * (size_t)i);
        __half2 a = __floats2half2_rn(v.x, v.y);
        __half2 b = __floats2half2_rn(v.z, v.w);
        *(uint2*)(Ah + 4 * (size_t)i) = make_uint2(h2_u32(a), h2_u32(b));
        return;
    }
    int xb = (bx - CVT_BLKS) / 64;      // 0..159 column block
    int ky = (bx - CVT_BLKS) % 64;      // k block
    const float* W; __half* out; int N, row_off;
    if (xb < 64)       { W = Wq; out = Oqkv; N = DIM; row_off = 0;         }
    else if (xb < 80)  { W = Wk; out = Oqkv; N = KVD; row_off = DIM;       xb -= 64; }
    else if (xb < 96)  { W = Wv; out = Oqkv; N = KVD; row_off = DIM + KVD; xb -= 80; }
    else               { W = Wo; out = Oo;   N = DIM; row_off = 0;         xb -= 96; }
    int k0 = ky * 32, n0 = xb * 32;
    int tx = threadIdx.x & 31, ty = threadIdx.x >> 5;   // 32 x 8
    #pragma unroll
    for (int i = 0; i < 32; i += 8)
        t[ty + i][tx] = W[(size_t)(k0 + ty + i) * N + n0 + tx];
    __syncthreads();
    #pragma unroll
    for (int i = 0; i < 32; i += 8) {
        int n = n0 + ty + i, k = k0 + tx;
        out[(size_t)(n + row_off) * DIM + k] = __float2half_rn(t[tx][ty + i]);
    }
}

// ======================= fp16 mma.sync GEMM ==================================
// C = A[M,K] @ B[N,K]^T, K=2048. CTA 128x256, 512 threads, 16 warps (4m x 4n),
// warp tile 32x64, BK=64, 4-stage cp.async, prefetch depth 2,
// ONE barrier per chunk. MODE 0: fp32 C out. MODE 1: fused QKV epilogue.
#define GSTRB 144                   // 128B data + 16B pad per row
#define ASUB  (128 * GSTRB)         // 18432
#define GSTG  (384 * GSTRB)         // 55296 (A 128 rows + B 256 rows)
#define GSMEM (4 * GSTG)            // 221184
#define GNIT  (DIM / 64)            // 32

template <int MODE>
__global__ __launch_bounds__(512) void gemm_h_kernel(
    const __half* __restrict__ A, const __half* __restrict__ B,
    float* __restrict__ C, int Ntot,
    const float* __restrict__ cs, const float* __restrict__ sn,
    __half* __restrict__ Qh, __half* __restrict__ Kh, __half* __restrict__ Vh)
{
    extern __shared__ __align__(16) char smbuf[];
    const uint32_t smBase = smem_u32(smbuf);

    const int tid = threadIdx.x;
    const int lane = tid & 31;
    const int wid = tid >> 5;
    const int wm = wid >> 2, wn = wid & 3;     // 4m x 4n warps
    const int m0 = blockIdx.y * 128;
    const int n0 = blockIdx.x * 256;

    const uint32_t offA = ((((lane >> 3) & 1) * 8 + (lane & 7)) * GSTRB) + ((lane >> 4) * 16);
    const uint32_t offB = (((lane >> 4) * 8 + (lane & 7)) * GSTRB) + (((lane >> 3) & 1) * 16);

    const char* Ab = (const char*)A;
    const char* Bb = (const char*)B;

    auto load_stage = [&](int kc, int slot) {
        uint32_t base = smBase + slot * GSTG;
        int kb = kc * 128;                      // 64 fp16 = 128 bytes per chunk
        #pragma unroll
        for (int j = 0; j < 2; j++) {           // A: 128 rows x 8 chunks = 1024
            int c = tid + j * 512;
            int row = c >> 3, col = (c & 7) * 16;
            cp16(base + row * GSTRB + col,
                 Ab + (size_t)(m0 + row) * WRB + kb + col);
        }
        #pragma unroll
        for (int j = 0; j < 4; j++) {           // B: 256 rows x 8 chunks = 2048
            int c = tid + j * 512;
            int row = c >> 3, col = (c & 7) * 16;
            cp16(base + ASUB + row * GSTRB + col,
                 Bb + (size_t)(n0 + row) * WRB + kb + col);
        }
        cp_commit();
    };

    float acc[2][8][4];
    #pragma unroll
    for (int i = 0; i < 2; i++)
        #pragma unroll
        for (int j = 0; j < 8; j++)
            #pragma unroll
            for (int k = 0; k < 4; k++) acc[i][j][k] = 0.f;

    load_stage(0, 0);
    load_stage(1, 1);

    for (int i = 0; i < GNIT; i++) {
        // prefetch depth 2 into 4 slots: writer slot (i+2)&3 can collide only
        // with readers of iteration i-2, which finished before barrier i-1.
        if (i + 2 < GNIT) { load_stage(i + 2, (i + 2) & 3); cp_wait<2>(); }
        else if (i + 2 == GNIT) cp_wait<1>();
        else cp_wait<0>();
        __syncthreads();

        uint32_t sA = smBase + (i & 3) * GSTG;
        uint32_t sB = sA + ASUB;
        #pragma unroll
        for (int ks = 0; ks < 4; ks++) {
            uint32_t bfr[4][4];
            #pragma unroll
            for (int nt2 = 0; nt2 < 4; nt2++)
                ldmx4(bfr[nt2], sB + (wn * 64 + nt2 * 16) * GSTRB + ks * 32 + offB);
            uint32_t afr[2][4];
            #pragma unroll
            for (int mt = 0; mt < 2; mt++)
                ldmx4(afr[mt], sA + (wm * 32 + mt * 16) * GSTRB + ks * 32 + offA);
            #pragma unroll
            for (int mt = 0; mt < 2; mt++)
                #pragma unroll
                for (int nt = 0; nt < 8; nt++)
                    mma_f16(acc[mt][nt], afr[mt], bfr[nt >> 1][(nt & 1) * 2],
                            bfr[nt >> 1][(nt & 1) * 2 + 1]);
        }
    }

    #pragma unroll
    for (int mt = 0; mt < 2; mt++) {
        int r0 = m0 + wm * 32 + mt * 16 + (lane >> 2);
        int r1 = r0 + 8;
        int s0 = r0 & (SEQ - 1), s1 = r1 & (SEQ - 1);
        #pragma unroll
        for (int nt = 0; nt < 8; nt++) {
            float a0 = acc[mt][nt][0], a1 = acc[mt][nt][1];
            float a2 = acc[mt][nt][2], a3 = acc[mt][nt][3];
            int c = n0 + wn * 64 + nt * 8 + (lane & 3) * 2;
            if (MODE == 0) {
                *(float2*)(C + (size_t)r0 * Ntot + c) = make_float2(a0, a1);
                *(float2*)(C + (size_t)r1 * Ntot + c) = make_float2(a2, a3);
            } else {
                if (n0 < DIM) {               // Q: rope + scale
                    int fi = (c & 127) >> 1;
                    float c0 = cs[s0 * 64 + fi], z0 = sn[s0 * 64 + fi];
                    float c1 = cs[s1 * 64 + fi], z1 = sn[s1 * 64 + fi];
                    *(__half2*)(Qh + (size_t)r0 * DIM + c) =
                        __floats2half2_rn((a0 * c0 - a1 * z0) * QMUL, (a0 * z0 + a1 * c0) * QMUL);
                    *(__half2*)(Qh + (size_t)r1 * DIM + c) =
                        __floats2half2_rn((a2 * c1 - a3 * z1) * QMUL, (a2 * z1 + a3 * c1) * QMUL);
                } else if (n0 < DIM + KVD) {  // K: rope
                    int ck = c - DIM;
                    int fi = (ck & 127) >> 1;
                    float c0 = cs[s0 * 64 + fi], z0 = sn[s0 * 64 + fi];
                    float c1 = cs[s1 * 64 + fi], z1 = sn[s1 * 64 + fi];
                    *(__half2*)(Kh + (size_t)r0 * KVD + ck) =
                        __floats2half2_rn(a0 * c0 - a1 * z0, a0 * z0 + a1 * c0);
                    *(__half2*)(Kh + (size_t)r1 * KVD + ck) =
                        __floats2half2_rn(a2 * c1 - a3 * z1, a2 * z1 + a3 * c1);
                } else {                      // V: cvt
                    int cv = c - DIM - KVD;
                    *(__half2*)(Vh + (size_t)r0 * KVD + cv) = __floats2half2_rn(a0, a1);
                    *(__half2*)(Vh + (size_t)r1 * KVD + cv) = __floats2half2_rn(a2, a3);
                }
            }
        }
    }
}

// ---------------- Flash attention (fp16 mma.sync, BN=128) --------------------
// smem: K0 | K1 (double-buffered, 34.8KB each) | V (single, 34.8KB; Q aliased
// here initially). 104.4KB -> 2 CTAs/SM. 128 threads (4 warps, 16 q-rows each).
#define FSTR 272
#define KTILE (128 * FSTR)              // 34816
#define FSMEM (3 * KTILE)               // 104448

__global__ __launch_bounds__(128, 2) void flash_mma_kernel(
    const __half* __restrict__ Q, const __half* __restrict__ K,
    const __half* __restrict__ V, __half* __restrict__ Ah)
{
    extern __shared__ char fsm[];
    const uint32_t TK0 = smem_u32(fsm);
    const uint32_t TK1 = TK0 + KTILE;
    const uint32_t TV  = TK0 + 2 * KTILE;

    const int tid = threadIdx.x;
    const int lane = tid & 31;
    const int wid = tid >> 5;
    const int qtile = gridDim.x - 1 - blockIdx.x;   // heavy tiles first
    const int h = blockIdx.y, b = blockIdx.z;
    const int g = h >> 2;
    const int m_base = qtile * 64;
    const int niter = (qtile + 2) >> 1;             // 128-key iterations

    const uint32_t offQ = ((((lane >> 3) & 1) * 8 + (lane & 7)) * FSTR) + ((lane >> 4) * 16);
    const uint32_t offK = (((lane >> 4) * 8 + (lane & 7)) * FSTR) + (((lane >> 3) & 1) * 16);

    const char* Qb = (const char*)Q;
    const char* Kb = (const char*)K;
    const char* Vb = (const char*)V;

    auto load_k = [&](int nt) {
        uint32_t dst = (nt & 1) ? TK1 : TK0;
        #pragma unroll
        for (int it = 0; it < 16; it++) {
            int c = it * 128 + tid;
            int row = c >> 4, col = c & 15;
            cp16(dst + row * FSTR + col * 16,
                 Kb + ((size_t)(b * SEQ + nt * 128 + row) * KVD + g * HD) * 2 + col * 16);
        }
        cp_commit();
    };
    auto load_v = [&](int nt) {
        #pragma unroll
        for (int it = 0; it < 16; it++) {
            int c = it * 128 + tid;
            int row = c >> 4, col = c & 15;
            cp16(TV + row * FSTR + col * 16,
                 Vb + ((size_t)(b * SEQ + nt * 128 + row) * KVD + g * HD) * 2 + col * 16);
        }
        cp_commit();
    };

    // Q tile -> TV (aliased; overwritten by V after fragment extraction)
    #pragma unroll
    for (int it = 0; it < 8; it++) {
        int c = it * 128 + tid;
        int row = c >> 4, col = c & 15;
        cp16(TV + row * FSTR + col * 16,
             Qb + ((size_t)(b * SEQ + m_base + row) * DIM + h * HD) * 2 + col * 16);
    }
    cp_commit();
    load_k(0);
    cp_wait<1>();                         // Q ready; K(0) may be in flight
    __syncthreads();

    uint32_t qfr[8][4];
    #pragma unroll
    for (int kd = 0; kd < 8; kd++)
        ldmx4(qfr[kd], TV + (wid * 16) * FSTR + kd * 32 + offQ);

    float acc[16][4];
    #pragma unroll
    for (int i = 0; i < 16; i++)
        #pragma unroll
        for (int j = 0; j < 4; j++) acc[i][j] = 0.f;
    float mr0 = -1e30f, mr1 = -1e30f, l0 = 0.f, l1 = 0.f;

    for (int nt = 0; nt < niter; nt++) {
        cp_wait<0>();                     // K(nt) resident; prior PV/qfr done
        __syncthreads();
        load_v(nt);                       // overwrites TV (safe after sync)
        bool haveNext = (nt + 1 < niter);
        if (haveNext) load_k(nt + 1);

        uint32_t smK = (nt & 1) ? TK1 : TK0;

        // S = Q @ K^T over 128 keys
        float s[16][4];
        #pragma unroll
        for (int i = 0; i < 16; i++)
            #pragma unroll
            for (int j = 0; j < 4; j++) s[i][j] = 0.f;
        #pragma unroll
        for (int kd = 0; kd < 8; kd++) {
            #pragma unroll
            for (int nt2 = 0; nt2 < 8; nt2++) {
                uint32_t bfr[4];
                ldmx4(bfr, smK + nt2 * 16 * FSTR + kd * 32 + offK);
                mma_f16(s[2 * nt2],     qfr[kd], bfr[0], bfr[1]);
                mma_f16(s[2 * nt2 + 1], qfr[kd], bfr[2], bfr[3]);
            }
        }

        if (nt == niter - 1) {            // causal mask (global indices)
            int rl0 = m_base + wid * 16 + (lane >> 2);
            int rl1 = rl0 + 8;
            #pragma unroll
            for (int kt = 0; kt < 16; kt++) {
                int cl = nt * 128 + kt * 8 + (lane & 3) * 2;
                if (cl     > rl0) s[kt][0] = -1e30f;
                if (cl + 1 > rl0) s[kt][1] = -1e30f;
                if (cl     > rl1) s[kt][2] = -1e30f;
                if (cl + 1 > rl1) s[kt][3] = -1e30f;
            }
        }

        float t0 = -1e30f, t1 = -1e30f;
        #pragma unroll
        for (int kt = 0; kt < 16; kt++) {
            t0 = fmaxf(t0, fmaxf(s[kt][0], s[kt][1]));
            t1 = fmaxf(t1, fmaxf(s[kt][2], s[kt][3]));
        }
        t0 = fmaxf(t0, __shfl_xor_sync(0xffffffffu, t0, 1));
        t0 = fmaxf(t0, __shfl_xor_sync(0xffffffffu, t0, 2));
        t1 = fmaxf(t1, __shfl_xor_sync(0xffffffffu, t1, 1));
        t1 = fmaxf(t1, __shfl_xor_sync(0xffffffffu, t1, 2));

        float mn0 = fmaxf(mr0, t0), mn1 = fmaxf(mr1, t1);
        float a0 = exp2f(mr0 - mn0), a1 = exp2f(mr1 - mn1);
        mr0 = mn0; mr1 = mn1;

        uint32_t pa[16][2];
        float lt0 = 0.f, lt1 = 0.f;
        #pragma unroll
        for (int kt = 0; kt < 16; kt++) {
            __half2 hp0 = h2exp2(__floats2half2_rn(s[kt][0] - mn0, s[kt][1] - mn0));
            __half2 hp1 = h2exp2(__floats2half2_rn(s[kt][2] - mn1, s[kt][3] - mn1));
            pa[kt][0] = h2_u32(hp0);
            pa[kt][1] = h2_u32(hp1);
            float2 f0 = __half22float2(hp0);
            float2 f1 = __half22float2(hp1);
            lt0 += f0.x + f0.y;
            lt1 += f1.x + f1.y;
        }
        lt0 += __shfl_xor_sync(0xffffffffu, lt0, 1);
        lt0 += __shfl_xor_sync(0xffffffffu, lt0, 2);
        lt1 += __shfl_xor_sync(0xffffffffu, lt1, 1);
        lt1 += __shfl_xor_sync(0xffffffffu, lt1, 2);
        l0 = l0 * a0 + lt0;
        l1 = l1 * a1 + lt1;

        // rescale accumulators (warp-uniform skip when all alphas == 1)
        if (!__all_sync(0xffffffffu, (a0 == 1.f) & (a1 == 1.f))) {
            #pragma unroll
            for (int i = 0; i < 16; i++) {
                acc[i][0] *= a0; acc[i][1] *= a0;
                acc[i][2] *= a1; acc[i][3] *= a1;
            }
        }

        if (haveNext) cp_wait<1>();       // V(nt) done; K(nt+1) may be pending
        else cp_wait<0>();
        __syncthreads();

        // O += P @ V  (k-dim = 128 keys)
        #pragma unroll
        for (int kt2 = 0; kt2 < 8; kt2++) {
            uint32_t pfr[4] = { pa[2 * kt2][0], pa[2 * kt2][1],
                                pa[2 * kt2 + 1][0], pa[2 * kt2 + 1][1] };
            #pragma unroll
            for (int dp = 0; dp < 8; dp++) {
                uint32_t vfr[4];
                ldmx4t(vfr, TV + kt2 * 16 * FSTR + dp * 32 + offQ);
                mma_f16(acc[2 * dp],     pfr, vfr[0], vfr[1]);
                mma_f16(acc[2 * dp + 1], pfr, vfr[2], vfr[3]);
            }
        }
    }

    // epilogue: normalize + plain fp16 into Ah [token, DIM]
    float inv0 = 1.f / l0, inv1 = 1.f / l1;
    int r0 = b * SEQ + m_base + wid * 16 + (lane >> 2);
    int r1 = r0 + 8;
    #pragma unroll
    for (int ntl = 0; ntl < 16; ntl++) {
        int c = h * HD + ntl * 8 + (lane & 3) * 2;
        *(__half2*)(Ah + (size_t)r0 * DIM + c) =
            __floats2half2_rn(acc[ntl][0] * inv0, acc[ntl][1] * inv0);
        *(__half2*)(Ah + (size_t)r1 * DIM + c) =
            __floats2half2_rn(acc[ntl][2] * inv1, acc[ntl][3] * inv1);
    }
}

// ---------------- launch -----------------------------------------------------
extern "C" void kernel_launch(void* const* d_in, const int* in_sizes, int n_in,
                              void* d_out, int out_size)
{
    const float* x  = (const float*)d_in[0];
    const float* fc = (const float*)d_in[1];
    const float* fs = (const float*)d_in[2];
    const float* Wq = (const float*)d_in[3];
    const float* Wk = (const float*)d_in[4];
    const float* Wv = (const float*)d_in[5];
    const float* Wo = (const float*)d_in[6];
    float* out = (float*)d_out;

    __half *Ah, *Wqkv, *Wo2, *Qh, *Kh, *Vh;
    cudaGetSymbolAddress((void**)&Ah,   g_Ah);
    cudaGetSymbolAddress((void**)&Wqkv, g_Wqkv);
    cudaGetSymbolAddress((void**)&Wo2,  g_Wo2);
    cudaGetSymbolAddress((void**)&Qh,   g_Qh);
    cudaGetSymbolAddress((void**)&Kh,   g_Kh);
    cudaGetSymbolAddress((void**)&Vh,   g_Vh);

    cudaFuncSetAttribute((const void*)gemm_h_kernel<0>,
                         cudaFuncAttributeMaxDynamicSharedMemorySize, GSMEM);
    cudaFuncSetAttribute((const void*)gemm_h_kernel<1>,
                         cudaFuncAttributeMaxDynamicSharedMemorySize, GSMEM);
    cudaFuncSetAttribute(flash_mma_kernel, cudaFuncAttributeMaxDynamicSharedMemorySize, FSMEM);

    // fused conversions (1 launch)
    prep_kernel<<<CVT_BLKS + 160 * 64, 256>>>(x, Wq, Wk, Wv, Wo, Ah, Wqkv, Wo2);

    // fused QKV projection + RoPE + fp16 convert
    gemm_h_kernel<1><<<dim3(NQKV / 256, MTOT / 128), 512, GSMEM>>>(
        Ah, Wqkv, nullptr, 0, fc, fs, Qh, Kh, Vh);

    // flash attention -> Ah fp16
    flash_mma_kernel<<<dim3(SEQ / 64, NH, BATCH), 128, FSMEM>>>(Qh, Kh, Vh, Ah);

    // output projection
    gemm_h_kernel<0><<<dim3(DIM / 256, MTOT / 128), 512, GSMEM>>>(
        Ah, Wo2, out, DIM, nullptr, nullptr, nullptr, nullptr, nullptr);
}